// round 5
// baseline (speedup 1.0000x reference)
#include <cuda_runtime.h>
#include <cstdint>

// ---------------------------------------------------------------------------
// Problem constants
// ---------------------------------------------------------------------------
#define T_STEPS 100
#define B_SZ    32
#define NIN     512
#define N_NEU   2048
#define A_AR    2
#define NC      4096                    // A*N output columns, c = a*2048+n
#define KROWS   4608                    // NIN + NC input rows
#define KCHUNK  144                     // 4608 / 32 k-chunks
#define NKC     32                      // number of k-chunks
#define NBY     8                       // k-splits (4 chunks each)
#define NBG     4                       // batch groups of 8
#define XIS_SZ  (T_STEPS * B_SZ * NIN)  // 1,638,400
#define SS_SZ   (T_STEPS * B_SZ * N_NEU)// 6,553,600 per area
// alpha = float32(exp(-0.1))
#define ALPHA_F 0.9048374180359595731642491f

// ---------------------------------------------------------------------------
// Device-global scratch (static — no allocation anywhere)
// b-major layouts for coalesced update-kernel access.
// ---------------------------------------------------------------------------
__device__ float g_W[KROWS * NC];        // fused weights [k][c], 75.5 MB
__device__ float g_sfb[B_SZ * KROWS];    // spike floats [b][k] for current step
__device__ float g_V[B_SZ * NC];         // membrane V [b][c]
__device__ float g_P[B_SZ * NC * NBY];   // partials [b*NC+c][by]

// ---------------------------------------------------------------------------
// Packed f32x2 helpers (sm_103a) — immune to fast-math contraction
// ---------------------------------------------------------------------------
__device__ __forceinline__ unsigned long long pack2(unsigned lo, unsigned hi) {
    unsigned long long d;
    asm("mov.b64 %0, {%1, %2};" : "=l"(d) : "r"(lo), "r"(hi));
    return d;
}
__device__ __forceinline__ unsigned long long ffma2(unsigned long long a,
                                                    unsigned long long b,
                                                    unsigned long long c) {
    unsigned long long d;
    asm("fma.rn.f32x2 %0, %1, %2, %3;" : "=l"(d) : "l"(a), "l"(b), "l"(c));
    return d;
}
__device__ __forceinline__ unsigned long long fadd2(unsigned long long a,
                                                    unsigned long long b) {
    unsigned long long d;
    asm("add.rn.f32x2 %0, %1, %2;" : "=l"(d) : "l"(a), "l"(b));
    return d;
}

// ---------------------------------------------------------------------------
// Kernel 1: Poisson input spikes for all T, straight into the Xis output
// region (layout [t][b][i]). Pure elementwise.
// ---------------------------------------------------------------------------
__global__ void __launch_bounds__(256) prep_spikes(const float* __restrict__ rates,
                                                   const float* __restrict__ noise,
                                                   float* __restrict__ out) {
    int idx = blockIdx.x * blockDim.x + threadIdx.x;
    if (idx >= XIS_SZ) return;
    float rt = rates[idx];
    float nz = noise[idx];
    out[idx] = (nz < __fmul_rn(rt, 1e-3f)) ? 1.0f : 0.0f;
}

// ---------------------------------------------------------------------------
// Kernel 2: fuse Win [A,NIN,N] and Wrec [S,A,N,N] into g_W[k][c].
// ---------------------------------------------------------------------------
__global__ void pack_w(const float* __restrict__ Win,
                       const float* __restrict__ Wrec) {
    const int total4 = KROWS * NC / 4;
    for (int idx = blockIdx.x * blockDim.x + threadIdx.x; idx < total4;
         idx += gridDim.x * blockDim.x) {
        int e = idx << 2;
        int k = e >> 12;              // / 4096
        int c = e & (NC - 1);
        int a = c >> 11;
        int n = c & (N_NEU - 1);
        float4 v;
        if (k < NIN) {
            v = *(const float4*)&Win[(a * NIN + k) * N_NEU + n];
        } else {
            int kr = k - NIN;
            int s  = kr >> 11;
            int m  = kr & (N_NEU - 1);
            v = *(const float4*)&Wrec[(((s * A_AR + a) * N_NEU) + m) * (size_t)N_NEU + n];
        }
        *(float4*)&g_W[e] = v;
    }
}

// ---------------------------------------------------------------------------
// Kernel 3: init: V = 0; g_sfb[b][k] = Xi(t=0) for ff rows, 0 for rec rows.
// ---------------------------------------------------------------------------
__global__ void __launch_bounds__(256) init_state(const float* __restrict__ out) {
    int idx = blockIdx.x * blockDim.x + threadIdx.x;
    if (idx < B_SZ * KROWS) {
        int b = idx / KROWS;
        int k = idx - b * KROWS;
        g_sfb[idx] = (k < NIN) ? out[b * NIN + k] : 0.0f;   // t=0 slice
    }
    if (idx < B_SZ * NC) g_V[idx] = 0.0f;
}

// ---------------------------------------------------------------------------
// Kernel B (per step): fused compact + sparse binary-spike GEMM partials.
// Grid: (32 col-tiles, 4 batch-groups, 8 by). Block: 8 warps = 4 ksub x 2 cw.
//
// Phase 1: warps 0..3 build the ascending active-k list for chunk by*4+warp
//   (active = integer OR of the 8 exact {0.0,1.0} batch spikes != 0).
// Phase 2: all 8 warps run the FMA loop over their ksub's list (ascending k);
//   thread covers 2 columns (LDG.64 on W) x 8 batches (4 f32x2 accs/col).
//   8 u64 accumulators -> low register pressure -> 4 blocks/SM (50% occ).
// Reduce: identical bit-exact tree to the passing R4 kernel: warp-per-chunk
//   ascending k, ksub folded ascending in-block, by folded ascending in
//   step_update. Only the thread->column mapping changed.
// ---------------------------------------------------------------------------
struct SmemP1 {
    unsigned list[4][KCHUNK];       // W byte offsets (k * NC * 4), ascending
    float    spk[4][KCHUNK][8];     // compacted spike floats
    int      cnt[4];
};
union SmemU {
    SmemP1 p1;
    unsigned long long sbuf[8][32][9];    // reduce buffer (8 u64 + pad)
};

__global__ void __launch_bounds__(256, 4) step_gemm() {
    __shared__ SmemU sm;

    const int w    = threadIdx.x >> 5;
    const int lane = threadIdx.x & 31;
    const int cw   = w & 1;          // column half within block
    const int ksub = w >> 1;         // 0..3
    const int bg   = blockIdx.y;     // batch group (8 batches)
    const int by   = blockIdx.z;     // partial index
    const int c0   = blockIdx.x * 128 + cw * 64 + lane * 2;

    // ---- Phase 1: warps 0..3 compact chunk (by*4 + w) for this bg ----
    if (w < 4) {
        const int kc = by * 4 + w;
        const int k0 = kc * KCHUNK;
        float    v[5][8];
        unsigned orv[5];
#pragma unroll
        for (int it = 0; it < 5; it++) {
            int r = it * 32 + lane;
            orv[it] = 0u;
#pragma unroll
            for (int b = 0; b < 8; b++) {
                float f = (r < KCHUNK) ? g_sfb[(bg * 8 + b) * KROWS + k0 + r] : 0.0f;
                v[it][b] = f;
                orv[it] |= __float_as_uint(f);
            }
        }
        int total = 0;
#pragma unroll
        for (int it = 0; it < 5; it++) {
            bool act = orv[it] != 0u;
            unsigned m = __ballot_sync(0xFFFFFFFFu, act);
            if (act) {
                int pos = total + __popc(m & ((1u << lane) - 1u));
                sm.p1.list[w][pos] = (unsigned)(k0 + it * 32 + lane) * (NC * 4);
#pragma unroll
                for (int b = 0; b < 8; b++) sm.p1.spk[w][pos][b] = v[it][b];
            }
            total += __popc(m);
        }
        if (lane == 0) sm.p1.cnt[w] = total;
    }
    __syncthreads();

    // ---- Phase 2: sparse FMA loop over this warp's chunk list ----
    const int n = sm.p1.cnt[ksub];
    const unsigned* __restrict__ lst = sm.p1.list[ksub];
    const float*    __restrict__ spk = &sm.p1.spk[ksub][0][0];
    const char* __restrict__ wbase = (const char*)g_W + (unsigned)c0 * 4u;

    unsigned long long acc[2][4];
#pragma unroll
    for (int c = 0; c < 2; c++)
#pragma unroll
        for (int j = 0; j < 4; j++) acc[c][j] = 0ull;

#pragma unroll 4
    for (int i = 0; i < n; i++) {
        unsigned off = lst[i];
        float2 wv = *(const float2*)(wbase + off);
        float4 sA = *(const float4*)&spk[i * 8];
        float4 sB = *(const float4*)&spk[i * 8 + 4];
        unsigned long long s2[4];
        s2[0] = pack2(__float_as_uint(sA.x), __float_as_uint(sA.y));
        s2[1] = pack2(__float_as_uint(sA.z), __float_as_uint(sA.w));
        s2[2] = pack2(__float_as_uint(sB.x), __float_as_uint(sB.y));
        s2[3] = pack2(__float_as_uint(sB.z), __float_as_uint(sB.w));
        unsigned long long w2a = pack2(__float_as_uint(wv.x), __float_as_uint(wv.x));
        unsigned long long w2b = pack2(__float_as_uint(wv.y), __float_as_uint(wv.y));
#pragma unroll
        for (int j = 0; j < 4; j++) {
            acc[0][j] = ffma2(w2a, s2[j], acc[0][j]);
            acc[1][j] = ffma2(w2b, s2[j], acc[1][j]);
        }
    }

    __syncthreads();   // all phase-1 data consumed; safe to reuse shared

#pragma unroll
    for (int c = 0; c < 2; c++)
#pragma unroll
        for (int j = 0; j < 4; j++) sm.sbuf[w][lane][c * 4 + j] = acc[c][j];
    __syncthreads();

    if (ksub == 0) {
#pragma unroll
        for (int ks = 1; ks < 4; ks++) {
#pragma unroll
            for (int c = 0; c < 2; c++)
#pragma unroll
                for (int j = 0; j < 4; j++)
                    acc[c][j] = fadd2(acc[c][j], sm.sbuf[ks * 2 + cw][lane][c * 4 + j]);
        }
#pragma unroll
        for (int c = 0; c < 2; c++) {
            int cc = c0 + c;
#pragma unroll
            for (int j = 0; j < 4; j++) {
                unsigned long long v = acc[c][j];
                float flo = __uint_as_float((unsigned)v);
                float fhi = __uint_as_float((unsigned)(v >> 32));
                int b = bg * 8 + 2 * j;
                g_P[(unsigned)((b)     * NC + cc) * NBY + by] = flo;
                g_P[(unsigned)((b + 1) * NC + cc) * NBY + by] = fhi;
            }
        }
    }
}

// ---------------------------------------------------------------------------
// Kernel C (per step): ordered reduce of 8 partials, LIF update, threshold,
// write spikes, refresh spike table for t+1. Thread = b*4096 + c -> every
// global access coalesced.
// ---------------------------------------------------------------------------
__global__ void __launch_bounds__(256) step_update(float* __restrict__ out, int t) {
    int idx = blockIdx.x * blockDim.x + threadIdx.x;   // 0 .. 131071
    if (idx >= B_SZ * NC) return;
    int b = idx >> 12;
    int c = idx & (NC - 1);

    const float4* p = (const float4*)&g_P[(size_t)idx * NBY];
    float4 u = p[0], v = p[1];
    float I = u.x;
    I = __fadd_rn(I, u.y);
    I = __fadd_rn(I, u.z);
    I = __fadd_rn(I, u.w);
    I = __fadd_rn(I, v.x);
    I = __fadd_rn(I, v.y);
    I = __fadd_rn(I, v.z);
    I = __fadd_rn(I, v.w);

    int sfi = b * KROWS + NIN + c;
    float xd   = g_sfb[sfi];            // previous spike of this neuron
    float Vold = g_V[idx];
    float Vnew = __fadd_rn(__fmul_rn(__fmul_rn(ALPHA_F, Vold), __fsub_rn(1.0f, xd)), I);
    float s = (Vnew >= 1.0f) ? 1.0f : 0.0f;

    g_V[idx] = Vnew;
    g_sfb[sfi] = s;                     // recurrent rows for step t+1

    int a = c >> 11;
    int n = c & (N_NEU - 1);
    out[XIS_SZ + a * SS_SZ + t * (B_SZ * N_NEU) + b * N_NEU + n] = s;

    // feedforward rows for step t+1 (read from the Xis region of out)
    if (c < NIN && t + 1 < T_STEPS)
        g_sfb[b * KROWS + c] = out[(t + 1) * (B_SZ * NIN) + b * NIN + c];
}

// ---------------------------------------------------------------------------
// Launch: prep (3 kernels) + 100 x (gemm, update). Graph-capturable.
// ---------------------------------------------------------------------------
extern "C" void kernel_launch(void* const* d_in, const int* in_sizes, int n_in,
                              void* d_out, int out_size) {
    const float* rates = (const float*)d_in[0];
    const float* noise = (const float*)d_in[1];
    const float* Win   = (const float*)d_in[2];
    const float* Wrec  = (const float*)d_in[3];
    float* out = (float*)d_out;

    prep_spikes<<<(XIS_SZ + 255) / 256, 256>>>(rates, noise, out);
    pack_w<<<1024, 256>>>(Win, Wrec);
    init_state<<<(B_SZ * KROWS + 255) / 256, 256>>>(out);

    for (int t = 0; t < T_STEPS; t++) {
        step_gemm<<<dim3(32, NBG, NBY), 256>>>();
        step_update<<<(B_SZ * NC) / 256, 256>>>(out, t);
    }
}

// round 6
// speedup vs baseline: 1.4167x; 1.4167x over previous
#include <cuda_runtime.h>
#include <cstdint>

// ---------------------------------------------------------------------------
// Problem constants
// ---------------------------------------------------------------------------
#define T_STEPS 100
#define B_SZ    32
#define NIN     512
#define N_NEU   2048
#define A_AR    2
#define NC      4096                    // A*N output columns, c = a*2048+n
#define KROWS   4608                    // NIN + NC input rows
#define KCHUNK  144                     // 4608 / 32 k-chunks
#define NKC     32                      // number of k-chunks
#define NBY     8                       // k-splits (4 chunks each)
#define NBG     4                       // batch groups of 8
#define XIS_SZ  (T_STEPS * B_SZ * NIN)  // 1,638,400
#define SS_SZ   (T_STEPS * B_SZ * N_NEU)// 6,553,600 per area
// alpha = float32(exp(-0.1))
#define ALPHA_F 0.9048374180359595731642491f

// ---------------------------------------------------------------------------
// Device-global scratch (static — no allocation anywhere)
// b-major layouts for coalesced update-kernel access.
// ---------------------------------------------------------------------------
__device__ float g_W[KROWS * NC];        // fused weights [k][c], 75.5 MB
__device__ float g_sfb[B_SZ * KROWS];    // spike floats [b][k] for current step
__device__ float g_V[B_SZ * NC];         // membrane V [b][c]
__device__ float g_P[B_SZ * NC * NBY];   // partials [b*NC+c][by]

// ---------------------------------------------------------------------------
// Packed f32x2 helpers (sm_103a) — immune to fast-math contraction
// ---------------------------------------------------------------------------
__device__ __forceinline__ unsigned long long pack2(unsigned lo, unsigned hi) {
    unsigned long long d;
    asm("mov.b64 %0, {%1, %2};" : "=l"(d) : "r"(lo), "r"(hi));
    return d;
}
__device__ __forceinline__ unsigned long long ffma2(unsigned long long a,
                                                    unsigned long long b,
                                                    unsigned long long c) {
    unsigned long long d;
    asm("fma.rn.f32x2 %0, %1, %2, %3;" : "=l"(d) : "l"(a), "l"(b), "l"(c));
    return d;
}
__device__ __forceinline__ unsigned long long fadd2(unsigned long long a,
                                                    unsigned long long b) {
    unsigned long long d;
    asm("add.rn.f32x2 %0, %1, %2;" : "=l"(d) : "l"(a), "l"(b));
    return d;
}

// ---------------------------------------------------------------------------
// Kernel 1: Poisson input spikes for all T, straight into the Xis output
// region (layout [t][b][i]). Pure elementwise.
// ---------------------------------------------------------------------------
__global__ void __launch_bounds__(256) prep_spikes(const float* __restrict__ rates,
                                                   const float* __restrict__ noise,
                                                   float* __restrict__ out) {
    int idx = blockIdx.x * blockDim.x + threadIdx.x;
    if (idx >= XIS_SZ) return;
    float rt = rates[idx];
    float nz = noise[idx];
    out[idx] = (nz < __fmul_rn(rt, 1e-3f)) ? 1.0f : 0.0f;
}

// ---------------------------------------------------------------------------
// Kernel 2: fuse Win [A,NIN,N] and Wrec [S,A,N,N] into g_W[k][c].
// ---------------------------------------------------------------------------
__global__ void pack_w(const float* __restrict__ Win,
                       const float* __restrict__ Wrec) {
    const int total4 = KROWS * NC / 4;
    for (int idx = blockIdx.x * blockDim.x + threadIdx.x; idx < total4;
         idx += gridDim.x * blockDim.x) {
        int e = idx << 2;
        int k = e >> 12;              // / 4096
        int c = e & (NC - 1);
        int a = c >> 11;
        int n = c & (N_NEU - 1);
        float4 v;
        if (k < NIN) {
            v = *(const float4*)&Win[(a * NIN + k) * N_NEU + n];
        } else {
            int kr = k - NIN;
            int s  = kr >> 11;
            int m  = kr & (N_NEU - 1);
            v = *(const float4*)&Wrec[(((s * A_AR + a) * N_NEU) + m) * (size_t)N_NEU + n];
        }
        *(float4*)&g_W[e] = v;
    }
}

// ---------------------------------------------------------------------------
// Kernel 3: init: V = 0; g_sfb[b][k] = Xi(t=0) for ff rows, 0 for rec rows.
// ---------------------------------------------------------------------------
__global__ void __launch_bounds__(256) init_state(const float* __restrict__ out) {
    int idx = blockIdx.x * blockDim.x + threadIdx.x;
    if (idx < B_SZ * KROWS) {
        int b = idx / KROWS;
        int k = idx - b * KROWS;
        g_sfb[idx] = (k < NIN) ? out[b * NIN + k] : 0.0f;   // t=0 slice
    }
    if (idx < B_SZ * NC) g_V[idx] = 0.0f;
}

// ---------------------------------------------------------------------------
// Kernel B (per step): fused compact + sparse binary-spike GEMM partials.
// Grid: (16 col-tiles, 4 batch-groups, 8 by). Block: 8 warps = 4 ksub x 2 cw.
//
// Phase 1: warps 0..3 build the ascending active-k list for chunk by*4+warp.
// Phase 2: all 8 warps run the FMA loop over their ksub's list (ascending k);
//   thread covers 4 columns (LDG.128 on W) x 8 batches (4 f32x2 accs/col).
//   Inner loop fetches 4 list offsets with one LDS.128 and issues 4
//   INDEPENDENT W loads before the FMAs -> 4x per-thread MLP on the L2 path.
//   FMA application order remains ascending i -> bit-identical to R4.
// Reduce: identical bit-exact tree (ksub ascending in-block, by ascending in
//   step_update).
// ---------------------------------------------------------------------------
struct SmemP1 {
    unsigned list[4][KCHUNK];       // W byte offsets (k * NC * 4), ascending
    float    spk[4][KCHUNK][8];     // compacted spike floats
    int      cnt[4];
};
union SmemU {
    SmemP1 p1;
    unsigned long long sbuf[8][32][17];   // reduce buffer (16 u64 + pad)
};

__device__ __forceinline__ void fma_row(unsigned long long acc[4][4],
                                        float4 wv, const float* __restrict__ sp) {
    float4 sA = *(const float4*)sp;
    float4 sB = *(const float4*)(sp + 4);
    unsigned long long s2[4];
    s2[0] = pack2(__float_as_uint(sA.x), __float_as_uint(sA.y));
    s2[1] = pack2(__float_as_uint(sA.z), __float_as_uint(sA.w));
    s2[2] = pack2(__float_as_uint(sB.x), __float_as_uint(sB.y));
    s2[3] = pack2(__float_as_uint(sB.z), __float_as_uint(sB.w));
    unsigned wb[4] = {__float_as_uint(wv.x), __float_as_uint(wv.y),
                      __float_as_uint(wv.z), __float_as_uint(wv.w)};
#pragma unroll
    for (int c = 0; c < 4; c++) {
        unsigned long long w2 = pack2(wb[c], wb[c]);
#pragma unroll
        for (int j = 0; j < 4; j++)
            acc[c][j] = ffma2(w2, s2[j], acc[c][j]);
    }
}

__global__ void __launch_bounds__(256, 3) step_gemm() {
    __shared__ SmemU sm;

    const int w    = threadIdx.x >> 5;
    const int lane = threadIdx.x & 31;
    const int cw   = w & 1;          // column half within block
    const int ksub = w >> 1;         // 0..3
    const int bg   = blockIdx.y;     // batch group (8 batches)
    const int by   = blockIdx.z;     // partial index
    const int c0   = blockIdx.x * 256 + cw * 128 + lane * 4;

    // ---- Phase 1: warps 0..3 compact chunk (by*4 + w) for this bg ----
    if (w < 4) {
        const int kc = by * 4 + w;
        const int k0 = kc * KCHUNK;
        float    v[5][8];
        unsigned orv[5];
#pragma unroll
        for (int it = 0; it < 5; it++) {
            int r = it * 32 + lane;
            orv[it] = 0u;
#pragma unroll
            for (int b = 0; b < 8; b++) {
                float f = (r < KCHUNK) ? g_sfb[(bg * 8 + b) * KROWS + k0 + r] : 0.0f;
                v[it][b] = f;
                orv[it] |= __float_as_uint(f);
            }
        }
        int total = 0;
#pragma unroll
        for (int it = 0; it < 5; it++) {
            bool act = orv[it] != 0u;
            unsigned m = __ballot_sync(0xFFFFFFFFu, act);
            if (act) {
                int pos = total + __popc(m & ((1u << lane) - 1u));
                sm.p1.list[w][pos] = (unsigned)(k0 + it * 32 + lane) * (NC * 4);
#pragma unroll
                for (int b = 0; b < 8; b++) sm.p1.spk[w][pos][b] = v[it][b];
            }
            total += __popc(m);
        }
        if (lane == 0) sm.p1.cnt[w] = total;
    }
    __syncthreads();

    // ---- Phase 2: sparse FMA loop, 4-row batched W prefetch ----
    const int n = sm.p1.cnt[ksub];
    const unsigned* __restrict__ lst = sm.p1.list[ksub];
    const float*    __restrict__ spk = &sm.p1.spk[ksub][0][0];
    const char* __restrict__ wbase = (const char*)g_W + (unsigned)c0 * 4u;

    unsigned long long acc[4][4];
#pragma unroll
    for (int c = 0; c < 4; c++)
#pragma unroll
        for (int j = 0; j < 4; j++) acc[c][j] = 0ull;

    int i = 0;
    for (; i + 4 <= n; i += 4) {
        uint4 off = *(const uint4*)&lst[i];           // one LDS.128: 4 offsets
        float4 wv0 = *(const float4*)(wbase + off.x); // 4 independent LDG.128
        float4 wv1 = *(const float4*)(wbase + off.y);
        float4 wv2 = *(const float4*)(wbase + off.z);
        float4 wv3 = *(const float4*)(wbase + off.w);
        fma_row(acc, wv0, &spk[(i + 0) * 8]);
        fma_row(acc, wv1, &spk[(i + 1) * 8]);
        fma_row(acc, wv2, &spk[(i + 2) * 8]);
        fma_row(acc, wv3, &spk[(i + 3) * 8]);
    }
    for (; i < n; i++) {
        unsigned off = lst[i];
        float4 wv = *(const float4*)(wbase + off);
        fma_row(acc, wv, &spk[i * 8]);
    }

    __syncthreads();   // all phase-1 data consumed; safe to reuse shared

#pragma unroll
    for (int c = 0; c < 4; c++)
#pragma unroll
        for (int j = 0; j < 4; j++) sm.sbuf[w][lane][c * 4 + j] = acc[c][j];
    __syncthreads();

    if (ksub == 0) {
#pragma unroll
        for (int ks = 1; ks < 4; ks++) {
#pragma unroll
            for (int c = 0; c < 4; c++)
#pragma unroll
                for (int j = 0; j < 4; j++)
                    acc[c][j] = fadd2(acc[c][j], sm.sbuf[ks * 2 + cw][lane][c * 4 + j]);
        }
#pragma unroll
        for (int c = 0; c < 4; c++) {
            int cc = c0 + c;
#pragma unroll
            for (int j = 0; j < 4; j++) {
                unsigned long long v = acc[c][j];
                float flo = __uint_as_float((unsigned)v);
                float fhi = __uint_as_float((unsigned)(v >> 32));
                int b = bg * 8 + 2 * j;
                g_P[(unsigned)((b)     * NC + cc) * NBY + by] = flo;
                g_P[(unsigned)((b + 1) * NC + cc) * NBY + by] = fhi;
            }
        }
    }
}

// ---------------------------------------------------------------------------
// Kernel C (per step): ordered reduce of 8 partials, LIF update, threshold,
// write spikes, refresh spike table for t+1. Thread = b*4096 + c -> every
// global access coalesced.
// ---------------------------------------------------------------------------
__global__ void __launch_bounds__(256) step_update(float* __restrict__ out, int t) {
    int idx = blockIdx.x * blockDim.x + threadIdx.x;   // 0 .. 131071
    if (idx >= B_SZ * NC) return;
    int b = idx >> 12;
    int c = idx & (NC - 1);

    const float4* p = (const float4*)&g_P[(size_t)idx * NBY];
    float4 u = p[0], v = p[1];
    float I = u.x;
    I = __fadd_rn(I, u.y);
    I = __fadd_rn(I, u.z);
    I = __fadd_rn(I, u.w);
    I = __fadd_rn(I, v.x);
    I = __fadd_rn(I, v.y);
    I = __fadd_rn(I, v.z);
    I = __fadd_rn(I, v.w);

    int sfi = b * KROWS + NIN + c;
    float xd   = g_sfb[sfi];            // previous spike of this neuron
    float Vold = g_V[idx];
    float Vnew = __fadd_rn(__fmul_rn(__fmul_rn(ALPHA_F, Vold), __fsub_rn(1.0f, xd)), I);
    float s = (Vnew >= 1.0f) ? 1.0f : 0.0f;

    g_V[idx] = Vnew;
    g_sfb[sfi] = s;                     // recurrent rows for step t+1

    int a = c >> 11;
    int n = c & (N_NEU - 1);
    out[XIS_SZ + a * SS_SZ + t * (B_SZ * N_NEU) + b * N_NEU + n] = s;

    // feedforward rows for step t+1 (read from the Xis region of out)
    if (c < NIN && t + 1 < T_STEPS)
        g_sfb[b * KROWS + c] = out[(t + 1) * (B_SZ * NIN) + b * NIN + c];
}

// ---------------------------------------------------------------------------
// Launch: prep (3 kernels) + 100 x (gemm, update). Graph-capturable.
// ---------------------------------------------------------------------------
extern "C" void kernel_launch(void* const* d_in, const int* in_sizes, int n_in,
                              void* d_out, int out_size) {
    const float* rates = (const float*)d_in[0];
    const float* noise = (const float*)d_in[1];
    const float* Win   = (const float*)d_in[2];
    const float* Wrec  = (const float*)d_in[3];
    float* out = (float*)d_out;

    prep_spikes<<<(XIS_SZ + 255) / 256, 256>>>(rates, noise, out);
    pack_w<<<1024, 256>>>(Win, Wrec);
    init_state<<<(B_SZ * KROWS + 255) / 256, 256>>>(out);

    for (int t = 0; t < T_STEPS; t++) {
        step_gemm<<<dim3(16, NBG, NBY), 256>>>();
        step_update<<<(B_SZ * NC) / 256, 256>>>(out, t);
    }
}

// round 8
// speedup vs baseline: 1.5367x; 1.0847x over previous
#include <cuda_runtime.h>
#include <cstdint>

// ---------------------------------------------------------------------------
// Problem constants
// ---------------------------------------------------------------------------
#define T_STEPS 100
#define B_SZ    32
#define NIN     512
#define N_NEU   2048
#define A_AR    2
#define NC      4096                    // A*N output columns, c = a*2048+n
#define KROWS   4608                    // NIN + NC input rows
#define KCHUNK  144                     // 4608 / 32 k-chunks
#define NKC     32                      // number of k-chunks
#define NBY     8                       // k-splits (4 chunks each)
#define NBG     4                       // batch groups of 8
#define XIS_SZ  (T_STEPS * B_SZ * NIN)  // 1,638,400
#define SS_SZ   (T_STEPS * B_SZ * N_NEU)// 6,553,600 per area
// alpha = float32(exp(-0.1))
#define ALPHA_F 0.9048374180359595731642491f

// ---------------------------------------------------------------------------
// Device-global scratch (static — no allocation anywhere)
// ---------------------------------------------------------------------------
__device__ float         g_W[KROWS * NC];              // fused weights [k][c]
__device__ float         g_V[B_SZ * NC];               // membrane V [b][c]
__device__ float         g_P[NBY * B_SZ * NC];         // partials [by][b][c]
__device__ unsigned char g_mff[T_STEPS * NBG * NIN];   // ff spike masks per t
__device__ unsigned char g_m8[NBG * KROWS];            // current-step masks [bg][k]

// ---------------------------------------------------------------------------
// Packed f32x2 helpers (sm_103a) — immune to fast-math contraction
// ---------------------------------------------------------------------------
__device__ __forceinline__ unsigned long long pack2(unsigned lo, unsigned hi) {
    unsigned long long d;
    asm("mov.b64 %0, {%1, %2};" : "=l"(d) : "r"(lo), "r"(hi));
    return d;
}
__device__ __forceinline__ unsigned long long ffma2(unsigned long long a,
                                                    unsigned long long b,
                                                    unsigned long long c) {
    unsigned long long d;
    asm("fma.rn.f32x2 %0, %1, %2, %3;" : "=l"(d) : "l"(a), "l"(b), "l"(c));
    return d;
}
__device__ __forceinline__ unsigned long long fadd2(unsigned long long a,
                                                    unsigned long long b) {
    unsigned long long d;
    asm("add.rn.f32x2 %0, %1, %2;" : "=l"(d) : "l"(a), "l"(b));
    return d;
}
__device__ __forceinline__ float lo32(unsigned long long v) {
    return __uint_as_float((unsigned)v);
}
__device__ __forceinline__ float hi32(unsigned long long v) {
    return __uint_as_float((unsigned)(v >> 32));
}

// ---------------------------------------------------------------------------
// Kernel 1: Poisson input spikes for all T -> Xis output region [t][b][i].
// ---------------------------------------------------------------------------
__global__ void __launch_bounds__(256) prep_spikes(const float* __restrict__ rates,
                                                   const float* __restrict__ noise,
                                                   float* __restrict__ out) {
    int idx = blockIdx.x * blockDim.x + threadIdx.x;
    if (idx >= XIS_SZ) return;
    float rt = rates[idx];
    float nz = noise[idx];
    out[idx] = (nz < __fmul_rn(rt, 1e-3f)) ? 1.0f : 0.0f;
}

// ---------------------------------------------------------------------------
// Kernel 1b: pack ff spike masks for all t: g_mff[t][bg][i] bit b = spike of
// batch bg*8+b. Exact: bit set iff the float is nonzero.
// ---------------------------------------------------------------------------
__global__ void __launch_bounds__(256) prep_masks(const float* __restrict__ out) {
    int idx = blockIdx.x * blockDim.x + threadIdx.x;    // t*NBG*NIN
    if (idx >= T_STEPS * NBG * NIN) return;
    int t  = idx / (NBG * NIN);
    int r  = idx - t * (NBG * NIN);
    int bg = r >> 9;
    int i  = r & (NIN - 1);
    unsigned m = 0;
#pragma unroll
    for (int b = 0; b < 8; b++) {
        float f = out[t * (B_SZ * NIN) + (bg * 8 + b) * NIN + i];
        m |= (f != 0.0f ? 1u : 0u) << b;
    }
    g_mff[idx] = (unsigned char)m;
}

// ---------------------------------------------------------------------------
// Kernel 2: fuse Win [A,NIN,N] and Wrec [S,A,N,N] into g_W[k][c].
// ---------------------------------------------------------------------------
__global__ void pack_w(const float* __restrict__ Win,
                       const float* __restrict__ Wrec) {
    const int total4 = KROWS * NC / 4;
    for (int idx = blockIdx.x * blockDim.x + threadIdx.x; idx < total4;
         idx += gridDim.x * blockDim.x) {
        int e = idx << 2;
        int k = e >> 12;              // / 4096
        int c = e & (NC - 1);
        int a = c >> 11;
        int n = c & (N_NEU - 1);
        float4 v;
        if (k < NIN) {
            v = *(const float4*)&Win[(a * NIN + k) * N_NEU + n];
        } else {
            int kr = k - NIN;
            int s  = kr >> 11;
            int m  = kr & (N_NEU - 1);
            v = *(const float4*)&Wrec[(((s * A_AR + a) * N_NEU) + m) * (size_t)N_NEU + n];
        }
        *(float4*)&g_W[e] = v;
    }
}

// ---------------------------------------------------------------------------
// Kernel 3: init: V = 0; g_m8 = [mff(t=0) | zero rec masks].
// ---------------------------------------------------------------------------
__global__ void __launch_bounds__(256) init_state() {
    int idx = blockIdx.x * blockDim.x + threadIdx.x;
    if (idx < NBG * KROWS) {
        int bg = idx / KROWS;
        int k  = idx - bg * KROWS;
        g_m8[idx] = (k < NIN) ? g_mff[bg * NIN + k] : (unsigned char)0;
    }
    if (idx < B_SZ * NC) g_V[idx] = 0.0f;
}

// ---------------------------------------------------------------------------
// Kernel B (per step): mask-driven compact + sparse binary-spike GEMM.
// Grid: (16 col-tiles, 4 bg, 8 by). Block: 8 warps = 4 ksub x 2 cw.
// Phase 1: warps 0..3 read 144 mask BYTES for chunk by*4+w (coalesced),
//   ballot-compact ascending-k active rows, expand mask bits to the exact
//   {0.0f, 1.0f} spike floats in shared (identical values to prior rounds).
// Phase 2: unchanged from R6 (4-row batched LDG.128 on W, ascending i).
// Reduce: identical bit-exact tree (ksub ascending in-block, by ascending in
//   step_update). Epilogue stores transposed g_P[by][b][c] as STG.128.
// ---------------------------------------------------------------------------
struct SmemP1 {
    unsigned list[4][KCHUNK];       // W byte offsets (k * NC * 4), ascending
    float    spk[4][KCHUNK][8];     // expanded spike floats
    int      cnt[4];
};
union SmemU {
    SmemP1 p1;
    unsigned long long sbuf[8][32][17];   // reduce buffer (16 u64 + pad)
};

__device__ __forceinline__ void fma_row(unsigned long long acc[4][4],
                                        float4 wv, const float* __restrict__ sp) {
    float4 sA = *(const float4*)sp;
    float4 sB = *(const float4*)(sp + 4);
    unsigned long long s2[4];
    s2[0] = pack2(__float_as_uint(sA.x), __float_as_uint(sA.y));
    s2[1] = pack2(__float_as_uint(sA.z), __float_as_uint(sA.w));
    s2[2] = pack2(__float_as_uint(sB.x), __float_as_uint(sB.y));
    s2[3] = pack2(__float_as_uint(sB.z), __float_as_uint(sB.w));
    unsigned wb[4] = {__float_as_uint(wv.x), __float_as_uint(wv.y),
                      __float_as_uint(wv.z), __float_as_uint(wv.w)};
#pragma unroll
    for (int c = 0; c < 4; c++) {
        unsigned long long w2 = pack2(wb[c], wb[c]);
#pragma unroll
        for (int j = 0; j < 4; j++)
            acc[c][j] = ffma2(w2, s2[j], acc[c][j]);
    }
}

__global__ void __launch_bounds__(256, 3) step_gemm() {
    __shared__ SmemU sm;

    const int w    = threadIdx.x >> 5;
    const int lane = threadIdx.x & 31;
    const int cw   = w & 1;          // column half within block
    const int ksub = w >> 1;         // 0..3
    const int bg   = blockIdx.y;     // batch group (8 batches)
    const int by   = blockIdx.z;     // partial index
    const int c0   = blockIdx.x * 256 + cw * 128 + lane * 4;

    // ---- Phase 1: warps 0..3 compact chunk (by*4 + w) for this bg ----
    if (w < 4) {
        const int kc = by * 4 + w;
        const int k0 = kc * KCHUNK;
        const unsigned char* __restrict__ mb = &g_m8[bg * KROWS + k0];
        int total = 0;
#pragma unroll
        for (int it = 0; it < 5; it++) {
            int r = it * 32 + lane;
            unsigned msk = (r < KCHUNK) ? (unsigned)mb[r] : 0u;
            bool act = msk != 0u;
            unsigned bal = __ballot_sync(0xFFFFFFFFu, act);
            if (act) {
                int pos = total + __popc(bal & ((1u << lane) - 1u));
                sm.p1.list[w][pos] = (unsigned)(k0 + r) * (NC * 4);
#pragma unroll
                for (int b = 0; b < 8; b++)
                    sm.p1.spk[w][pos][b] = (msk >> b) & 1u ? 1.0f : 0.0f;
            }
            total += __popc(bal);
        }
        if (lane == 0) sm.p1.cnt[w] = total;
    }
    __syncthreads();

    // ---- Phase 2: sparse FMA loop, 4-row batched W prefetch ----
    const int n = sm.p1.cnt[ksub];
    const unsigned* __restrict__ lst = sm.p1.list[ksub];
    const float*    __restrict__ spk = &sm.p1.spk[ksub][0][0];
    const char* __restrict__ wbase = (const char*)g_W + (unsigned)c0 * 4u;

    unsigned long long acc[4][4];
#pragma unroll
    for (int c = 0; c < 4; c++)
#pragma unroll
        for (int j = 0; j < 4; j++) acc[c][j] = 0ull;

    int i = 0;
    for (; i + 4 <= n; i += 4) {
        uint4 off = *(const uint4*)&lst[i];           // one LDS.128: 4 offsets
        float4 wv0 = *(const float4*)(wbase + off.x); // 4 independent LDG.128
        float4 wv1 = *(const float4*)(wbase + off.y);
        float4 wv2 = *(const float4*)(wbase + off.z);
        float4 wv3 = *(const float4*)(wbase + off.w);
        fma_row(acc, wv0, &spk[(i + 0) * 8]);
        fma_row(acc, wv1, &spk[(i + 1) * 8]);
        fma_row(acc, wv2, &spk[(i + 2) * 8]);
        fma_row(acc, wv3, &spk[(i + 3) * 8]);
    }
    for (; i < n; i++) {
        unsigned off = lst[i];
        float4 wv = *(const float4*)(wbase + off);
        fma_row(acc, wv, &spk[i * 8]);
    }

    __syncthreads();   // all phase-1 data consumed; safe to reuse shared

#pragma unroll
    for (int c = 0; c < 4; c++)
#pragma unroll
        for (int j = 0; j < 4; j++) sm.sbuf[w][lane][c * 4 + j] = acc[c][j];
    __syncthreads();

    if (ksub == 0) {
#pragma unroll
        for (int ks = 1; ks < 4; ks++) {
#pragma unroll
            for (int c = 0; c < 4; c++)
#pragma unroll
                for (int j = 0; j < 4; j++)
                    acc[c][j] = fadd2(acc[c][j], sm.sbuf[ks * 2 + cw][lane][c * 4 + j]);
        }
        // transposed, coalesced stores: g_P[by][b][c0..c0+3]
#pragma unroll
        for (int j = 0; j < 4; j++) {
            int b = bg * 8 + 2 * j;
            float4 lo4 = make_float4(lo32(acc[0][j]), lo32(acc[1][j]),
                                     lo32(acc[2][j]), lo32(acc[3][j]));
            float4 hi4 = make_float4(hi32(acc[0][j]), hi32(acc[1][j]),
                                     hi32(acc[2][j]), hi32(acc[3][j]));
            *(float4*)&g_P[(unsigned)((by * B_SZ + b)     * NC) + c0] = lo4;
            *(float4*)&g_P[(unsigned)((by * B_SZ + b + 1) * NC) + c0] = hi4;
        }
    }
}

// ---------------------------------------------------------------------------
// Kernel C (per step): thread = (bg, c) owns all 8 batches of its group.
// Ordered by-ascending reduce of 8 partials, LIF update, threshold, output
// writes, new recurrent mask byte, ff mask copy for t+1. All coalesced.
// ---------------------------------------------------------------------------
__global__ void __launch_bounds__(256) step_update(float* __restrict__ out, int t) {
    int idx = blockIdx.x * blockDim.x + threadIdx.x;   // 0 .. 16383
    if (idx >= NBG * NC) return;
    int bg = idx >> 12;
    int c  = idx & (NC - 1);
    int a  = c >> 11;
    int n  = c & (N_NEU - 1);

    unsigned oldm = g_m8[bg * KROWS + NIN + c];   // previous spikes (8 batches)
    unsigned newm = 0;

#pragma unroll
    for (int b8 = 0; b8 < 8; b8++) {
        int b = bg * 8 + b8;
        float I = g_P[(0 * B_SZ + b) * NC + c];
#pragma unroll
        for (int by = 1; by < NBY; by++)
            I = __fadd_rn(I, g_P[(by * B_SZ + b) * NC + c]);

        float xd   = (oldm >> b8) & 1u ? 1.0f : 0.0f;
        float Vold = g_V[b * NC + c];
        float Vnew = __fadd_rn(__fmul_rn(__fmul_rn(ALPHA_F, Vold),
                                         __fsub_rn(1.0f, xd)), I);
        unsigned s = Vnew >= 1.0f ? 1u : 0u;
        g_V[b * NC + c] = Vnew;
        newm |= s << b8;
        out[XIS_SZ + a * SS_SZ + t * (B_SZ * N_NEU) + b * N_NEU + n] =
            s ? 1.0f : 0.0f;
    }

    g_m8[bg * KROWS + NIN + c] = (unsigned char)newm;
    if (c < NIN && t + 1 < T_STEPS)
        g_m8[bg * KROWS + c] = g_mff[((t + 1) * NBG + bg) * NIN + c];
}

// ---------------------------------------------------------------------------
// Launch: prep (4 kernels) + 100 x (gemm, update). Graph-capturable.
// ---------------------------------------------------------------------------
extern "C" void kernel_launch(void* const* d_in, const int* in_sizes, int n_in,
                              void* d_out, int out_size) {
    const float* rates = (const float*)d_in[0];
    const float* noise = (const float*)d_in[1];
    const float* Win   = (const float*)d_in[2];
    const float* Wrec  = (const float*)d_in[3];
    float* out = (float*)d_out;

    prep_spikes<<<(XIS_SZ + 255) / 256, 256>>>(rates, noise, out);
    prep_masks<<<(T_STEPS * NBG * NIN + 255) / 256, 256>>>(out);
    pack_w<<<1024, 256>>>(Win, Wrec);
    init_state<<<(B_SZ * NC + 255) / 256, 256>>>();

    for (int t = 0; t < T_STEPS; t++) {
        step_gemm<<<dim3(16, NBG, NBY), 256>>>();
        step_update<<<(NBG * NC + 255) / 256, 256>>>(out, t);
    }
}